// round 15
// baseline (speedup 1.0000x reference)
#include <cuda_runtime.h>
#include <cuda_bf16.h>
#include <mma.h>
#include <stdint.h>

using namespace nvcuda;

#define NB  4
#define C   256
#define CI  128
#define NHW 4096
// theta scale: sqrt(128) (reference divides by d**-0.5) * log2(e) (attn uses ex2)
#define SCALE2 16.32374202690664f

// Scratch (allocation-free). Q/K/G (and Wo) stored PRE-SWIZZLED: within each
// row, 16B chunk c is stored at position c ^ (row & 7). Tiles become
// contiguous blocks for cp.async.bulk and conflict-free for ldmatrix.
__device__ __nv_bfloat16 g_W[C * 384];         // fused weights, [c][o] (theta|phi|g)
__device__ float         g_bias[384];
__device__ __nv_bfloat16 g_Wo[CI * 256];       // w_out transposed bf16, [cc][o] (swizzled)
__device__ __nv_bfloat16 g_Q[NB * NHW * CI];   // theta, pre-scaled by SCALE2 (swizzled)
__device__ __nv_bfloat16 g_K[NB * NHW * CI];   // phi (swizzled)
__device__ __nv_bfloat16 g_G[NB * NHW * CI];   // g (swizzled)

// ---------------------------------------------------------------------------
// helpers
// ---------------------------------------------------------------------------
__device__ __forceinline__ uint32_t pack2(float a, float b) {
    __nv_bfloat162 h = __floats2bfloat162_rn(a, b);
    return *reinterpret_cast<uint32_t*>(&h);
}
__device__ __forceinline__ float ex2f(float x) {
    float y;
    asm("ex2.approx.f32 %0, %1;" : "=f"(y) : "f"(x));
    return y;
}
__device__ __forceinline__ void ldsm_x4(uint32_t* f, uint32_t addr) {
    asm volatile("ldmatrix.sync.aligned.m8n8.x4.shared.b16 {%0,%1,%2,%3}, [%4];"
                 : "=r"(f[0]), "=r"(f[1]), "=r"(f[2]), "=r"(f[3]) : "r"(addr));
}
__device__ __forceinline__ void ldsm_x4_t(uint32_t* f, uint32_t addr) {
    asm volatile("ldmatrix.sync.aligned.m8n8.x4.trans.shared.b16 {%0,%1,%2,%3}, [%4];"
                 : "=r"(f[0]), "=r"(f[1]), "=r"(f[2]), "=r"(f[3]) : "r"(addr));
}
__device__ __forceinline__ void mma16816(float* c, const uint32_t* a,
                                         uint32_t b0, uint32_t b1) {
    asm volatile("mma.sync.aligned.m16n8k16.row.col.f32.bf16.bf16.f32 "
                 "{%0,%1,%2,%3}, {%4,%5,%6,%7}, {%8,%9}, {%0,%1,%2,%3};"
                 : "+f"(c[0]), "+f"(c[1]), "+f"(c[2]), "+f"(c[3])
                 : "r"(a[0]), "r"(a[1]), "r"(a[2]), "r"(a[3]), "r"(b0), "r"(b1));
}
__device__ __forceinline__ void cp_async16(uint32_t dst, const void* src) {
    asm volatile("cp.async.cg.shared.global [%0], [%1], 16;" :: "r"(dst), "l"(src));
}
__device__ __forceinline__ void cp_commit() { asm volatile("cp.async.commit_group;"); }
template <int N>
__device__ __forceinline__ void cp_wait() {
    asm volatile("cp.async.wait_group %0;" :: "n"(N) : "memory");
}
// 1D bulk copy, global -> shared, mbarrier completion (sm_90 baseline PTX)
__device__ __forceinline__ void cp_bulk(uint32_t dst, const void* src,
                                        uint32_t bytes, uint32_t mbar) {
    asm volatile(
        "cp.async.bulk.shared::cluster.global.mbarrier::complete_tx::bytes "
        "[%0], [%1], %2, [%3];"
        :: "r"(dst), "l"(src), "r"(bytes), "r"(mbar) : "memory");
}

#define MBARRIER_INIT(mbar, cnt) \
    asm volatile("mbarrier.init.shared.b64 [%0], %1;" \
                 :: "r"((uint32_t)(mbar)), "r"((uint32_t)(cnt)) : "memory")
#define MBARRIER_EXPECT_TX(mbar, tx) \
    asm volatile("mbarrier.arrive.expect_tx.shared.b64 _, [%0], %1;" \
                 :: "r"((uint32_t)(mbar)), "r"((uint32_t)(tx)) : "memory")
#define MBARRIER_ARRIVE(mbar) \
    asm volatile("mbarrier.arrive.shared.b64 _, [%0];" \
                 :: "r"((uint32_t)(mbar)) : "memory")
#define MBARRIER_WAIT_PARITY(mbar, parity) do { \
    uint32_t _m = (uint32_t)(mbar); uint32_t _p = (uint32_t)(parity); uint32_t _d; \
    asm volatile("{\n\t.reg .pred p;\n\t" \
        "mbarrier.try_wait.parity.acquire.cta.shared::cta.b64 p, [%1], %2;\n\t" \
        "selp.b32 %0, 1, 0, p;\n\t}" : "=r"(_d) : "r"(_m), "r"(_p) : "memory"); \
    if (!_d) { \
        asm volatile("{\n\t.reg .pred P1;\n\t" \
            "WAIT_LOOP_%=:\n\t" \
            "mbarrier.try_wait.parity.acquire.cta.shared::cta.b64 P1, [%0], %1, 0x989680;\n\t" \
            "@P1 bra.uni WAIT_DONE_%=;\n\t" \
            "bra.uni WAIT_LOOP_%=;\n\t" \
            "WAIT_DONE_%=:\n\t}" :: "r"(_m), "r"(_p) : "memory"); \
    } \
} while (0)

// ---------------------------------------------------------------------------
// Kernel 0: weight conversions only (x handled directly by proj now).
//   blocks [0,256):   fused weights -> g_W bf16 [c][384] + bias
//   blocks [256,384): w_out -> g_Wo bf16 [cc][o] (chunk-swizzled)
// ---------------------------------------------------------------------------
__global__ void __launch_bounds__(256) cvt_w_kernel(
        const float* __restrict__ w_theta, const float* __restrict__ b_theta,
        const float* __restrict__ w_phi,   const float* __restrict__ b_phi,
        const float* __restrict__ w_g,     const float* __restrict__ b_g,
        const float* __restrict__ w_out)
{
    const int blk = blockIdx.x;
    const int t = threadIdx.x;
    if (blk < 256) {
        const int c = blk;
        for (int o = t; o < 384; o += 256) {
            float v, bv;
            if (o < 128)      { v = w_theta[o * C + c] * SCALE2;  bv = b_theta[o] * SCALE2; }
            else if (o < 256) { v = w_phi[(o - 128) * C + c];     bv = b_phi[o - 128]; }
            else              { v = w_g[(o - 256) * C + c];       bv = b_g[o - 256]; }
            g_W[c * 384 + o] = __float2bfloat16(v);
            if (c == 0) g_bias[o] = bv;
        }
    } else {
        const int cc = blk - 256;              // 0..127
        const int o = t;                       // 0..255
        int phys = (((o >> 3) ^ (cc & 7)) << 3) + (o & 7);
        g_Wo[cc * 256 + phys] = __float2bfloat16(w_out[o * CI + cc]);
    }
}

// ---------------------------------------------------------------------------
// Kernel 1: projections GEMM, reading x DIRECTLY as fp32 (no pre-pass).
// Per 64-c chunk: wait staged fp32 X + bf16 W; convert X to bf16 in smem;
// MMA; THEN prefetch chunk+2 (after sync -- prefetch targets the same-parity
// buffers the MMA just finished reading). Commit only real groups; last
// chunk waits for all.
// grid (64 stile, 2 nsplit, 4 b), 256 threads. dyn smem = 95232 B.
// ---------------------------------------------------------------------------
__global__ void __launch_bounds__(256) proj_kernel(const float* __restrict__ x)
{
    extern __shared__ char sm[];
    uint32_t sb = (uint32_t)__cvta_generic_to_shared(sm);
    // Xf (fp32 staging): 2 x [64][68] f32 = 17408 B each
    const uint32_t xf0 = sb;
    const uint32_t xf1 = sb + 17408;
    // Xb (bf16 MMA tile): [64][72] bf16 = 9216 B (single buffer)
    __nv_bfloat16* Xb16 = (__nv_bfloat16*)(sm + 34816);
    // W: 2 x [64][200] bf16 = 25600 B each
    const uint32_t ws0 = sb + 44032;
    const uint32_t ws1 = sb + 69632;
    float* St = (float*)sm;                         // [64][200] fp32 (reuse)

    const int s0 = blockIdx.x * 64;
    const int ng = blockIdx.y;
    const int b  = blockIdx.z;
    const int t  = threadIdx.x;
    const int warp = t >> 5;
    const int wm = warp >> 1;
    const int wn = warp & 1;

    const float* Xg = x + (size_t)b * C * NHW;

    auto prefetch = [&](int c0, uint32_t xd, uint32_t wd) {
#pragma unroll
        for (int i = 0; i < 4; i++) {          // X fp32: 1024 chunks of 16B
            int idx = t + i * 256;
            int rr = idx >> 4, c4 = (idx & 15) * 4;
            cp_async16(xd + (uint32_t)(rr * 68 + c4) * 4,
                       Xg + (size_t)(c0 + rr) * NHW + s0 + c4);
        }
#pragma unroll
        for (int i = 0; i < 6; i++) {          // W: 1536 chunks
            int idx = t + i * 256;
            int rr = idx / 24, o8 = (idx % 24) * 8;
            cp_async16(wd + (rr * 200 + o8) * 2, g_W + (c0 + rr) * 384 + ng * 192 + o8);
        }
    };
    prefetch(0, xf0, ws0);  cp_commit();
    prefetch(64, xf1, ws1); cp_commit();

    wmma::fragment<wmma::accumulator, 16, 16, 16, float> acc[6];
#pragma unroll
    for (int j = 0; j < 6; j++) wmma::fill_fragment(acc[j], 0.0f);

    for (int kc = 0; kc < 4; kc++) {
        if (kc < 3) cp_wait<1>(); else cp_wait<0>();
        __syncthreads();                       // chunk kc staged; prev MMA done

        // convert Xf (fp32 [c][s], pitch 68) -> Xb16 (bf16 [c][s], pitch 72)
        const float* Xf = (const float*)(sm + ((kc & 1) ? 17408 : 0));
#pragma unroll
        for (int i = 0; i < 8; i++) {
            int idx = t + i * 256;             // 2048 s-pairs
            int cc = idx >> 5, sp = (idx & 31) * 2;
            float2 v = *(const float2*)(Xf + cc * 68 + sp);
            *(uint32_t*)(Xb16 + cc * 72 + sp) = pack2(v.x, v.y);
        }
        __syncthreads();                       // Xb ready

        const __nv_bfloat16* Ws = (const __nv_bfloat16*)(sm + 44032 + ((kc & 1) ? 25600 : 0));
#pragma unroll
        for (int kk = 0; kk < 4; kk++) {
            wmma::fragment<wmma::matrix_a, 16, 16, 16, __nv_bfloat16, wmma::col_major> af;
            wmma::load_matrix_sync(af, Xb16 + (kk * 16) * 72 + wm * 16, 72);
#pragma unroll
            for (int j = 0; j < 6; j++) {
                wmma::fragment<wmma::matrix_b, 16, 16, 16, __nv_bfloat16, wmma::row_major> bf;
                wmma::load_matrix_sync(bf, Ws + (kk * 16) * 200 + wn * 96 + j * 16, 200);
                wmma::mma_sync(acc[j], af, bf, acc[j]);
            }
        }

        if (kc + 2 < 4) {
            __syncthreads();                   // ALL warps done reading Xf/Ws[kc&1]
            prefetch((kc + 2) * 64, (kc & 1) ? xf1 : xf0, (kc & 1) ? ws1 : ws0);
            cp_commit();
        }
    }
    __syncthreads();

#pragma unroll
    for (int j = 0; j < 6; j++)
        wmma::store_matrix_sync(St + (wm * 16) * 200 + wn * 96 + j * 16, acc[j], 200,
                                wmma::mem_row_major);
    __syncthreads();

    // bias + route to Q/K/G, paired stores. Swizzle: chunk (col>>3)^(row&7);
    // col even -> phys,phys+1 stay adjacent within the same 8-elem group.
    for (int i = 0; i < 24; i++) {
        int idx = t + i * 256;               // 6144 = 64s * 96 col-pairs
        int ss = idx / 96;
        int op = idx % 96;
        int oc = op * 2;
        int ocg = ng * 192 + oc;
        float v0 = St[ss * 200 + oc]     + g_bias[ocg];
        float v1 = St[ss * 200 + oc + 1] + g_bias[ocg + 1];
        uint32_t w = pack2(v0, v1);
        size_t base = ((size_t)b * NHW + s0 + ss) * CI;
        int r7 = ss & 7;                     // (s0+ss)&7 == ss&7, s0 mult of 64
        int col = (ocg < 128) ? ocg : (ocg < 256 ? ocg - 128 : ocg - 256);
        int phys = (((col >> 3) ^ r7) << 3) + (col & 7);
        if (ocg < 128)       *(uint32_t*)&g_Q[base + phys] = w;
        else if (ocg < 256)  *(uint32_t*)&g_K[base + phys] = w;
        else                 *(uint32_t*)&g_G[base + phys] = w;
    }
}

// ---------------------------------------------------------------------------
// Kernel 2: warp-specialized flash attention WITH FUSED OUTPUT PROJECTION.
// Identical to the round-13 PASSING version (producer __syncwarp fix).
// grid (32, 4) = 128 CTAs, 288 threads, dyn smem = 164864 B.
// ---------------------------------------------------------------------------
__global__ void __launch_bounds__(288) attn_kernel(
        const float* __restrict__ x,
        const float* __restrict__ b_out, float* __restrict__ out)
{
    extern __shared__ char sm[];
    uint32_t sb = (uint32_t)__cvta_generic_to_shared(sm);
    const uint32_t MBQ = sb;             // Q ready barrier
    const uint32_t RDY = sb + 16;        // ready[4] at +16,+24,+32,+40
    const uint32_t CSM = sb + 64;        // consumed[4] at +64,+72,+80,+88
    const uint32_t QS  = sb + 1024;      // Q / later Y: 128 rows x 256B = 32768
    auto kstage = [&](int s) { return QS + 32768u + (uint32_t)s * 32768u; };
    auto gstage = [&](int s) { return QS + 32768u + (uint32_t)s * 32768u + 16384u; };
    const uint32_t WOS = QS + 32768u;    // Wo (epilogue): 128 x 512B = 65536 (stages 0-1)

    const int b  = blockIdx.y;
    const int q0 = blockIdx.x * 128;
    const int t  = threadIdx.x;
    const int warp = t >> 5;
    const int lane = t & 31;
    const int mi = lane >> 3;
    const int r8 = lane & 7;
    const int rA = lane >> 2;
    const int cA = (lane & 3) * 2;

    const __nv_bfloat16* Qg = g_Q + ((size_t)b * NHW + q0) * CI;
    const __nv_bfloat16* Kb = g_K + (size_t)b * NHW * CI;
    const __nv_bfloat16* Gb = g_G + (size_t)b * NHW * CI;

    if (t == 0) {
        MBARRIER_INIT(MBQ, 1);
#pragma unroll
        for (int s = 0; s < 4; s++) {
            MBARRIER_INIT(RDY + 8 * s, 1);
            MBARRIER_INIT(CSM + 8 * s, 256);   // 8 consumer warps x 32 lanes
        }
    }
    __syncthreads();

    uint32_t qa[8][4];                    // Q fragments; reused for Y fragments

    if (warp == 8) {
        // ---------------- producer warp ----------------
        if (lane == 0) {
            MBARRIER_EXPECT_TX(MBQ, 32768);
            cp_bulk(QS, Qg, 32768, MBQ);
            for (int kt = 0; kt < 64; kt++) {
                int s = kt & 3;
                if (kt >= 4)
                    MBARRIER_WAIT_PARITY(CSM + 8 * s, ((kt >> 2) + 1) & 1);
                MBARRIER_EXPECT_TX(RDY + 8 * s, 32768);
                cp_bulk(kstage(s), Kb + (size_t)kt * 64 * CI, 16384, RDY + 8 * s);
                cp_bulk(gstage(s), Gb + (size_t)kt * 64 * CI, 16384, RDY + 8 * s);
            }
        }
        // Order ALL producer lanes behind lane 0's sequential phase
        // observations; only then does parity-1 uniquely mean phase 15.
        __syncwarp();
        MBARRIER_WAIT_PARITY(CSM + 8 * 0, 1);
        MBARRIER_WAIT_PARITY(CSM + 8 * 1, 1);
        for (int idx = lane; idx < 4096; idx += 32)
            cp_async16(WOS + (uint32_t)idx * 16, g_Wo + idx * 8);
        cp_commit();
        cp_wait<0>();
    } else {
        // ---------------- consumer warps (0..7) ----------------
        MBARRIER_WAIT_PARITY(MBQ, 0);

        // Q A-fragments: rows [warp*16, warp*16+16), 8 k-chunks of 16
        {
            int Rq = warp * 16 + (mi & 1) * 8 + r8;
            uint32_t qb = QS + (uint32_t)Rq * 256;
            int s7 = Rq & 7;
#pragma unroll
            for (int kc = 0; kc < 8; kc++)
                ldsm_x4(qa[kc], qb + (uint32_t)(((kc * 2 + (mi >> 1)) ^ s7) << 4));
        }

        float O[16][4];
#pragma unroll
        for (int n = 0; n < 16; n++)
#pragma unroll
            for (int j = 0; j < 4; j++) O[n][j] = 0.0f;
        float rs0 = 0.0f, rs1 = 0.0f;

        const int Rk_ = (mi >> 1) * 8 + r8;   // K fragment row (+ p*16)
        const int Rg_ = (mi & 1) * 8 + r8;    // G fragment row (+ p*16)
        const int ck_ = (mi & 1);             // K chunk offset
        const int cg_ = (mi >> 1);            // G chunk offset

        for (int kt = 0; kt < 64; kt++) {
            const int s = kt & 3;
            MBARRIER_WAIT_PARITY(RDY + 8 * s, (kt >> 2) & 1);
            const uint32_t kb = kstage(s);
            const uint32_t gb = gstage(s);

            // S = Q @ K^T  (16 x 64 per warp, in registers)
            float S[8][4];
#pragma unroll
            for (int n = 0; n < 8; n++)
#pragma unroll
                for (int j = 0; j < 4; j++) S[n][j] = 0.0f;

#pragma unroll
            for (int p = 0; p < 4; p++) {
                const int Rk = p * 16 + Rk_;
                const uint32_t kbp = kb + (uint32_t)Rk * 256;
                const int s7 = Rk & 7;
#pragma unroll
                for (int kc = 0; kc < 8; kc++) {
                    uint32_t f[4];
                    ldsm_x4(f, kbp + (uint32_t)(((kc * 2 + ck_) ^ s7) << 4));
                    mma16816(S[2 * p],     qa[kc], f[0], f[1]);
                    mma16816(S[2 * p + 1], qa[kc], f[2], f[3]);
                }
            }

            // P = exp2(S); pack to bf16x2 A-fragments; accumulate row sums
            uint32_t pa[4][4];
#pragma unroll
            for (int p = 0; p < 4; p++) {
                float e00 = ex2f(S[2 * p][0]),     e01 = ex2f(S[2 * p][1]);
                float e02 = ex2f(S[2 * p][2]),     e03 = ex2f(S[2 * p][3]);
                float e10 = ex2f(S[2 * p + 1][0]), e11 = ex2f(S[2 * p + 1][1]);
                float e12 = ex2f(S[2 * p + 1][2]), e13 = ex2f(S[2 * p + 1][3]);
                rs0 += (e00 + e01) + (e10 + e11);
                rs1 += (e02 + e03) + (e12 + e13);
                pa[p][0] = pack2(e00, e01);
                pa[p][1] = pack2(e02, e03);
                pa[p][2] = pack2(e10, e11);
                pa[p][3] = pack2(e12, e13);
            }

            // O += P @ G  (16 x 128 per warp)
#pragma unroll
            for (int p = 0; p < 4; p++) {
                const int Rg = p * 16 + Rg_;
                const uint32_t gbp = gb + (uint32_t)Rg * 256;
                const int s7 = Rg & 7;
#pragma unroll
                for (int j2 = 0; j2 < 8; j2++) {
                    uint32_t f[4];
                    ldsm_x4_t(f, gbp + (uint32_t)(((j2 * 2 + cg_) ^ s7) << 4));
                    mma16816(O[2 * j2],     pa[p], f[0], f[1]);
                    mma16816(O[2 * j2 + 1], pa[p], f[2], f[3]);
                }
            }

            MBARRIER_ARRIVE(CSM + 8 * s);      // all 32 lanes arrive
        }

        // finalize: row sums, normalize, write Y (bf16, swizzled) to Q region
        rs0 += __shfl_xor_sync(0xffffffff, rs0, 1);
        rs0 += __shfl_xor_sync(0xffffffff, rs0, 2);
        rs1 += __shfl_xor_sync(0xffffffff, rs1, 1);
        rs1 += __shfl_xor_sync(0xffffffff, rs1, 2);
        const float inv0 = 1.0f / rs0;
        const float inv1 = 1.0f / rs1;

        {
            int R0 = warp * 16 + rA;
            int R1 = R0 + 8;
            char* y0 = sm + 1024 + R0 * 256;
            char* y1 = sm + 1024 + R1 * 256;
            int x0 = R0 & 7, x1 = R1 & 7;
#pragma unroll
            for (int n = 0; n < 16; n++) {
                *(uint32_t*)(y0 + ((n ^ x0) << 4) + cA * 2) =
                    pack2(O[n][0] * inv0, O[n][1] * inv0);
                *(uint32_t*)(y1 + ((n ^ x1) << 4) + cA * 2) =
                    pack2(O[n][2] * inv1, O[n][3] * inv1);
            }
        }
        __syncwarp();

        // reload qa as Y fragments (same rows, same addressing as Q)
        {
            int Rq = warp * 16 + (mi & 1) * 8 + r8;
            uint32_t qb = QS + (uint32_t)Rq * 256;
            int s7 = Rq & 7;
#pragma unroll
            for (int kc = 0; kc < 8; kc++)
                ldsm_x4(qa[kc], qb + (uint32_t)(((kc * 2 + (mi >> 1)) ^ s7) << 4));
        }
    }

    // single barrier: Wo resident (producer waited cp groups) + Y fragments held
    __syncthreads();
    if (warp == 8) return;                 // producer done

    // ---------------- fused output projection ----------------
    // out[b,o,q0+s] = x[b,o,q0+s] + b_out[o] + sum_c Y[s][c]*Wo[c][o]
    const float* xb = x + (size_t)b * C * NHW + q0;
    float*       ob = out + (size_t)b * C * NHW + q0;
    const int Rg_ = (mi & 1) * 8 + r8;     // Wo fragment row (+ p*16)
    const int cg_ = (mi >> 1);             // Wo chunk offset
    const int sA0 = warp * 16 + rA;        // s for c[0],c[1]
    const int sA1 = sA0 + 8;               // s for c[2],c[3]

#pragma unroll
    for (int j2 = 0; j2 < 16; j2++) {      // 16 o-tiles of 16
        float c0[4] = {0.f, 0.f, 0.f, 0.f};
        float c1[4] = {0.f, 0.f, 0.f, 0.f};
#pragma unroll
        for (int p = 0; p < 8; p++) {      // k = c, 8 chunks of 16
            const int Rc = p * 16 + Rg_;
            uint32_t a = WOS + (uint32_t)Rc * 512 +
                         (uint32_t)(((j2 * 2 + cg_) ^ (Rc & 7)) << 4);
            uint32_t f[4];
            ldsm_x4_t(f, a);
            mma16816(c0, qa[p], f[0], f[1]);
            mma16816(c1, qa[p], f[2], f[3]);
        }
        const int o0 = j2 * 16 + cA;       // cols o0, o0+1
        const int o1 = o0 + 8;             // cols o1, o1+1
        float b0 = b_out[o0], b0p = b_out[o0 + 1];
        float b1 = b_out[o1], b1p = b_out[o1 + 1];
        ob[(size_t)o0 * NHW + sA0]       = c0[0] + b0  + xb[(size_t)o0 * NHW + sA0];
        ob[(size_t)(o0 + 1) * NHW + sA0] = c0[1] + b0p + xb[(size_t)(o0 + 1) * NHW + sA0];
        ob[(size_t)o0 * NHW + sA1]       = c0[2] + b0  + xb[(size_t)o0 * NHW + sA1];
        ob[(size_t)(o0 + 1) * NHW + sA1] = c0[3] + b0p + xb[(size_t)(o0 + 1) * NHW + sA1];
        ob[(size_t)o1 * NHW + sA0]       = c1[0] + b1  + xb[(size_t)o1 * NHW + sA0];
        ob[(size_t)(o1 + 1) * NHW + sA0] = c1[1] + b1p + xb[(size_t)(o1 + 1) * NHW + sA0];
        ob[(size_t)o1 * NHW + sA1]       = c1[2] + b1  + xb[(size_t)o1 * NHW + sA1];
        ob[(size_t)(o1 + 1) * NHW + sA1] = c1[3] + b1p + xb[(size_t)(o1 + 1) * NHW + sA1];
    }
}

// ---------------------------------------------------------------------------
extern "C" void kernel_launch(void* const* d_in, const int* in_sizes, int n_in,
                              void* d_out, int out_size)
{
    const float* x       = (const float*)d_in[0];
    const float* w_g     = (const float*)d_in[1];
    const float* b_g     = (const float*)d_in[2];
    const float* w_theta = (const float*)d_in[3];
    const float* b_theta = (const float*)d_in[4];
    const float* w_phi   = (const float*)d_in[5];
    const float* b_phi   = (const float*)d_in[6];
    const float* w_out   = (const float*)d_in[7];
    const float* b_out   = (const float*)d_in[8];
    float* out = (float*)d_out;

    cudaFuncSetAttribute(proj_kernel, cudaFuncAttributeMaxDynamicSharedMemorySize, 95232);
    cudaFuncSetAttribute(attn_kernel, cudaFuncAttributeMaxDynamicSharedMemorySize, 164864);

    cvt_w_kernel<<<384, 256>>>(w_theta, b_theta, w_phi, b_phi, w_g, b_g, w_out);

    dim3 pgrid(64, 2, NB);
    proj_kernel<<<pgrid, 256, 95232>>>(x);

    dim3 agrid(32, NB);
    attn_kernel<<<agrid, 288, 164864>>>(x, b_out, out);
}

// round 16
// speedup vs baseline: 1.0002x; 1.0002x over previous
#include <cuda_runtime.h>
#include <cuda_bf16.h>
#include <mma.h>
#include <stdint.h>

using namespace nvcuda;

#define NB  4
#define C   256
#define CI  128
#define NHW 4096
// theta scale: sqrt(128) (reference divides by d**-0.5) * log2(e) (attn uses ex2)
#define SCALE2 16.32374202690664f

// Scratch (allocation-free). Q/K/G (and Wo) stored PRE-SWIZZLED: within each
// row, 16B chunk c is stored at position c ^ (row & 7). Tiles become
// contiguous blocks for cp.async.bulk and conflict-free for ldmatrix.
__device__ __nv_bfloat16 g_W[C * 384];         // fused weights, [c][o] (theta|phi|g)
__device__ float         g_bias[384];
__device__ __nv_bfloat16 g_Wo[CI * 256];       // w_out transposed bf16, [cc][o] (swizzled)
__device__ __nv_bfloat16 g_Q[NB * NHW * CI];   // theta, pre-scaled by SCALE2 (swizzled)
__device__ __nv_bfloat16 g_K[NB * NHW * CI];   // phi (swizzled)
__device__ __nv_bfloat16 g_G[NB * NHW * CI];   // g (swizzled)

// ---------------------------------------------------------------------------
// helpers
// ---------------------------------------------------------------------------
__device__ __forceinline__ uint32_t pack2(float a, float b) {
    __nv_bfloat162 h = __floats2bfloat162_rn(a, b);
    return *reinterpret_cast<uint32_t*>(&h);
}
__device__ __forceinline__ float ex2f(float x) {
    float y;
    asm("ex2.approx.f32 %0, %1;" : "=f"(y) : "f"(x));
    return y;
}
__device__ __forceinline__ void ldsm_x4(uint32_t* f, uint32_t addr) {
    asm volatile("ldmatrix.sync.aligned.m8n8.x4.shared.b16 {%0,%1,%2,%3}, [%4];"
                 : "=r"(f[0]), "=r"(f[1]), "=r"(f[2]), "=r"(f[3]) : "r"(addr));
}
__device__ __forceinline__ void ldsm_x4_t(uint32_t* f, uint32_t addr) {
    asm volatile("ldmatrix.sync.aligned.m8n8.x4.trans.shared.b16 {%0,%1,%2,%3}, [%4];"
                 : "=r"(f[0]), "=r"(f[1]), "=r"(f[2]), "=r"(f[3]) : "r"(addr));
}
__device__ __forceinline__ void mma16816(float* c, const uint32_t* a,
                                         uint32_t b0, uint32_t b1) {
    asm volatile("mma.sync.aligned.m16n8k16.row.col.f32.bf16.bf16.f32 "
                 "{%0,%1,%2,%3}, {%4,%5,%6,%7}, {%8,%9}, {%0,%1,%2,%3};"
                 : "+f"(c[0]), "+f"(c[1]), "+f"(c[2]), "+f"(c[3])
                 : "r"(a[0]), "r"(a[1]), "r"(a[2]), "r"(a[3]), "r"(b0), "r"(b1));
}
__device__ __forceinline__ void cp_async16(uint32_t dst, const void* src) {
    asm volatile("cp.async.cg.shared.global [%0], [%1], 16;" :: "r"(dst), "l"(src));
}
__device__ __forceinline__ void cp_commit() { asm volatile("cp.async.commit_group;"); }
template <int N>
__device__ __forceinline__ void cp_wait() {
    asm volatile("cp.async.wait_group %0;" :: "n"(N) : "memory");
}
// 1D bulk copy, global -> shared, mbarrier completion (sm_90 baseline PTX)
__device__ __forceinline__ void cp_bulk(uint32_t dst, const void* src,
                                        uint32_t bytes, uint32_t mbar) {
    asm volatile(
        "cp.async.bulk.shared::cluster.global.mbarrier::complete_tx::bytes "
        "[%0], [%1], %2, [%3];"
        :: "r"(dst), "l"(src), "r"(bytes), "r"(mbar) : "memory");
}

#define MBARRIER_INIT(mbar, cnt) \
    asm volatile("mbarrier.init.shared.b64 [%0], %1;" \
                 :: "r"((uint32_t)(mbar)), "r"((uint32_t)(cnt)) : "memory")
#define MBARRIER_EXPECT_TX(mbar, tx) \
    asm volatile("mbarrier.arrive.expect_tx.shared.b64 _, [%0], %1;" \
                 :: "r"((uint32_t)(mbar)), "r"((uint32_t)(tx)) : "memory")
#define MBARRIER_ARRIVE(mbar) \
    asm volatile("mbarrier.arrive.shared.b64 _, [%0];" \
                 :: "r"((uint32_t)(mbar)) : "memory")
#define MBARRIER_WAIT_PARITY(mbar, parity) do { \
    uint32_t _m = (uint32_t)(mbar); uint32_t _p = (uint32_t)(parity); uint32_t _d; \
    asm volatile("{\n\t.reg .pred p;\n\t" \
        "mbarrier.try_wait.parity.acquire.cta.shared::cta.b64 p, [%1], %2;\n\t" \
        "selp.b32 %0, 1, 0, p;\n\t}" : "=r"(_d) : "r"(_m), "r"(_p) : "memory"); \
    if (!_d) { \
        asm volatile("{\n\t.reg .pred P1;\n\t" \
            "WAIT_LOOP_%=:\n\t" \
            "mbarrier.try_wait.parity.acquire.cta.shared::cta.b64 P1, [%0], %1, 0x989680;\n\t" \
            "@P1 bra.uni WAIT_DONE_%=;\n\t" \
            "bra.uni WAIT_LOOP_%=;\n\t" \
            "WAIT_DONE_%=:\n\t}" :: "r"(_m), "r"(_p) : "memory"); \
    } \
} while (0)

// ---------------------------------------------------------------------------
// Kernel 0: weight conversions via coalesced 32x32 smem-tile transposes.
//   blocks [0,96):    g_W    (8 c-tiles x 12 o-tiles of the fused [384o][256c])
//   blocks [96,128):  g_Wo   (4 cc-tiles x 8 o-tiles of w_out [256o][128cc])
//   block  128:       bias vector
// ---------------------------------------------------------------------------
__global__ void __launch_bounds__(256) cvt_w_kernel(
        const float* __restrict__ w_theta, const float* __restrict__ b_theta,
        const float* __restrict__ w_phi,   const float* __restrict__ b_phi,
        const float* __restrict__ w_g,     const float* __restrict__ b_g,
        const float* __restrict__ w_out)
{
    __shared__ float tile[32][33];
    const int blk = blockIdx.x;
    const int t = threadIdx.x;

    if (blk < 96) {
        // g_W[c*384+o] = fused[o][c] (theta*SCALE2 | phi | g)
        const int ct = blk & 7;          // c-tile 0..7
        const int ot = blk >> 3;         // o-tile 0..11
        const int c0 = ct * 32, o0 = ot * 32;
        // load coalesced over c
#pragma unroll
        for (int i = 0; i < 4; i++) {
            int idx = t + i * 256;
            int oo = idx >> 5, cc = idx & 31;
            int o = o0 + oo;
            float v;
            if (o < 128)      v = w_theta[o * C + c0 + cc] * SCALE2;
            else if (o < 256) v = w_phi[(o - 128) * C + c0 + cc];
            else              v = w_g[(o - 256) * C + c0 + cc];
            tile[oo][cc] = v;
        }
        __syncthreads();
        // write coalesced over o
#pragma unroll
        for (int i = 0; i < 4; i++) {
            int idx = t + i * 256;
            int cc = idx >> 5, oo = idx & 31;
            g_W[(c0 + cc) * 384 + o0 + oo] = __float2bfloat16(tile[oo][cc]);
        }
    } else if (blk < 128) {
        // g_Wo[cc*256+phys(o,cc)] = w_out[o][cc], chunk-swizzled rows
        const int b2 = blk - 96;
        const int ccT = b2 & 3;          // cc-tile 0..3
        const int oT  = b2 >> 2;         // o-tile 0..7
        const int cc0 = ccT * 32, o0 = oT * 32;
#pragma unroll
        for (int i = 0; i < 4; i++) {
            int idx = t + i * 256;
            int oo = idx >> 5, cc = idx & 31;
            tile[oo][cc] = w_out[(o0 + oo) * CI + cc0 + cc];
        }
        __syncthreads();
#pragma unroll
        for (int i = 0; i < 4; i++) {
            int idx = t + i * 256;
            int cc = idx >> 5, oo = idx & 31;
            int o = o0 + oo;
            int ccg = cc0 + cc;
            int phys = (((o >> 3) ^ (ccg & 7)) << 3) + (o & 7);
            g_Wo[ccg * 256 + phys] = __float2bfloat16(tile[oo][cc]);
        }
    } else {
        for (int o = t; o < 384; o += 256) {
            float bv;
            if (o < 128)      bv = b_theta[o] * SCALE2;
            else if (o < 256) bv = b_phi[o - 128];
            else              bv = b_g[o - 256];
            g_bias[o] = bv;
        }
    }
}

// ---------------------------------------------------------------------------
// Kernel 1: projections GEMM, reading x DIRECTLY as fp32 (no pre-pass).
// Per 64-c chunk: wait staged fp32 X + bf16 W; convert X to bf16 in smem;
// MMA; THEN prefetch chunk+2 (after sync). Identical to round-15 passing.
// grid (64 stile, 2 nsplit, 4 b), 256 threads. dyn smem = 95232 B.
// ---------------------------------------------------------------------------
__global__ void __launch_bounds__(256) proj_kernel(const float* __restrict__ x)
{
    extern __shared__ char sm[];
    uint32_t sb = (uint32_t)__cvta_generic_to_shared(sm);
    const uint32_t xf0 = sb;
    const uint32_t xf1 = sb + 17408;
    __nv_bfloat16* Xb16 = (__nv_bfloat16*)(sm + 34816);
    const uint32_t ws0 = sb + 44032;
    const uint32_t ws1 = sb + 69632;
    float* St = (float*)sm;                         // [64][200] fp32 (reuse)

    const int s0 = blockIdx.x * 64;
    const int ng = blockIdx.y;
    const int b  = blockIdx.z;
    const int t  = threadIdx.x;
    const int warp = t >> 5;
    const int wm = warp >> 1;
    const int wn = warp & 1;

    const float* Xg = x + (size_t)b * C * NHW;

    auto prefetch = [&](int c0, uint32_t xd, uint32_t wd) {
#pragma unroll
        for (int i = 0; i < 4; i++) {          // X fp32: 1024 chunks of 16B
            int idx = t + i * 256;
            int rr = idx >> 4, c4 = (idx & 15) * 4;
            cp_async16(xd + (uint32_t)(rr * 68 + c4) * 4,
                       Xg + (size_t)(c0 + rr) * NHW + s0 + c4);
        }
#pragma unroll
        for (int i = 0; i < 6; i++) {          // W: 1536 chunks
            int idx = t + i * 256;
            int rr = idx / 24, o8 = (idx % 24) * 8;
            cp_async16(wd + (rr * 200 + o8) * 2, g_W + (c0 + rr) * 384 + ng * 192 + o8);
        }
    };
    prefetch(0, xf0, ws0);  cp_commit();
    prefetch(64, xf1, ws1); cp_commit();

    wmma::fragment<wmma::accumulator, 16, 16, 16, float> acc[6];
#pragma unroll
    for (int j = 0; j < 6; j++) wmma::fill_fragment(acc[j], 0.0f);

    for (int kc = 0; kc < 4; kc++) {
        if (kc < 3) cp_wait<1>(); else cp_wait<0>();
        __syncthreads();                       // chunk kc staged; prev MMA done

        // convert Xf (fp32 [c][s], pitch 68) -> Xb16 (bf16 [c][s], pitch 72)
        const float* Xf = (const float*)(sm + ((kc & 1) ? 17408 : 0));
#pragma unroll
        for (int i = 0; i < 8; i++) {
            int idx = t + i * 256;             // 2048 s-pairs
            int cc = idx >> 5, sp = (idx & 31) * 2;
            float2 v = *(const float2*)(Xf + cc * 68 + sp);
            *(uint32_t*)(Xb16 + cc * 72 + sp) = pack2(v.x, v.y);
        }
        __syncthreads();                       // Xb ready

        const __nv_bfloat16* Ws = (const __nv_bfloat16*)(sm + 44032 + ((kc & 1) ? 25600 : 0));
#pragma unroll
        for (int kk = 0; kk < 4; kk++) {
            wmma::fragment<wmma::matrix_a, 16, 16, 16, __nv_bfloat16, wmma::col_major> af;
            wmma::load_matrix_sync(af, Xb16 + (kk * 16) * 72 + wm * 16, 72);
#pragma unroll
            for (int j = 0; j < 6; j++) {
                wmma::fragment<wmma::matrix_b, 16, 16, 16, __nv_bfloat16, wmma::row_major> bf;
                wmma::load_matrix_sync(bf, Ws + (kk * 16) * 200 + wn * 96 + j * 16, 200);
                wmma::mma_sync(acc[j], af, bf, acc[j]);
            }
        }

        if (kc + 2 < 4) {
            __syncthreads();                   // ALL warps done reading Xf/Ws[kc&1]
            prefetch((kc + 2) * 64, (kc & 1) ? xf1 : xf0, (kc & 1) ? ws1 : ws0);
            cp_commit();
        }
    }
    __syncthreads();

#pragma unroll
    for (int j = 0; j < 6; j++)
        wmma::store_matrix_sync(St + (wm * 16) * 200 + wn * 96 + j * 16, acc[j], 200,
                                wmma::mem_row_major);
    __syncthreads();

    // bias + route to Q/K/G, paired stores. Swizzle: chunk (col>>3)^(row&7).
    for (int i = 0; i < 24; i++) {
        int idx = t + i * 256;               // 6144 = 64s * 96 col-pairs
        int ss = idx / 96;
        int op = idx % 96;
        int oc = op * 2;
        int ocg = ng * 192 + oc;
        float v0 = St[ss * 200 + oc]     + g_bias[ocg];
        float v1 = St[ss * 200 + oc + 1] + g_bias[ocg + 1];
        uint32_t w = pack2(v0, v1);
        size_t base = ((size_t)b * NHW + s0 + ss) * CI;
        int r7 = ss & 7;
        int col = (ocg < 128) ? ocg : (ocg < 256 ? ocg - 128 : ocg - 256);
        int phys = (((col >> 3) ^ r7) << 3) + (col & 7);
        if (ocg < 128)       *(uint32_t*)&g_Q[base + phys] = w;
        else if (ocg < 256)  *(uint32_t*)&g_K[base + phys] = w;
        else                 *(uint32_t*)&g_G[base + phys] = w;
    }
}

// ---------------------------------------------------------------------------
// Kernel 2: warp-specialized flash attention WITH FUSED OUTPUT PROJECTION.
// Identical to the round-13/15 PASSING version (producer __syncwarp fix).
// grid (32, 4) = 128 CTAs, 288 threads, dyn smem = 164864 B.
// ---------------------------------------------------------------------------
__global__ void __launch_bounds__(288) attn_kernel(
        const float* __restrict__ x,
        const float* __restrict__ b_out, float* __restrict__ out)
{
    extern __shared__ char sm[];
    uint32_t sb = (uint32_t)__cvta_generic_to_shared(sm);
    const uint32_t MBQ = sb;             // Q ready barrier
    const uint32_t RDY = sb + 16;        // ready[4] at +16,+24,+32,+40
    const uint32_t CSM = sb + 64;        // consumed[4] at +64,+72,+80,+88
    const uint32_t QS  = sb + 1024;      // Q / later Y: 128 rows x 256B = 32768
    auto kstage = [&](int s) { return QS + 32768u + (uint32_t)s * 32768u; };
    auto gstage = [&](int s) { return QS + 32768u + (uint32_t)s * 32768u + 16384u; };
    const uint32_t WOS = QS + 32768u;    // Wo (epilogue): 128 x 512B = 65536 (stages 0-1)

    const int b  = blockIdx.y;
    const int q0 = blockIdx.x * 128;
    const int t  = threadIdx.x;
    const int warp = t >> 5;
    const int lane = t & 31;
    const int mi = lane >> 3;
    const int r8 = lane & 7;
    const int rA = lane >> 2;
    const int cA = (lane & 3) * 2;

    const __nv_bfloat16* Qg = g_Q + ((size_t)b * NHW + q0) * CI;
    const __nv_bfloat16* Kb = g_K + (size_t)b * NHW * CI;
    const __nv_bfloat16* Gb = g_G + (size_t)b * NHW * CI;

    if (t == 0) {
        MBARRIER_INIT(MBQ, 1);
#pragma unroll
        for (int s = 0; s < 4; s++) {
            MBARRIER_INIT(RDY + 8 * s, 1);
            MBARRIER_INIT(CSM + 8 * s, 256);   // 8 consumer warps x 32 lanes
        }
    }
    __syncthreads();

    uint32_t qa[8][4];                    // Q fragments; reused for Y fragments

    if (warp == 8) {
        // ---------------- producer warp ----------------
        if (lane == 0) {
            MBARRIER_EXPECT_TX(MBQ, 32768);
            cp_bulk(QS, Qg, 32768, MBQ);
            for (int kt = 0; kt < 64; kt++) {
                int s = kt & 3;
                if (kt >= 4)
                    MBARRIER_WAIT_PARITY(CSM + 8 * s, ((kt >> 2) + 1) & 1);
                MBARRIER_EXPECT_TX(RDY + 8 * s, 32768);
                cp_bulk(kstage(s), Kb + (size_t)kt * 64 * CI, 16384, RDY + 8 * s);
                cp_bulk(gstage(s), Gb + (size_t)kt * 64 * CI, 16384, RDY + 8 * s);
            }
        }
        // Order ALL producer lanes behind lane 0's sequential phase
        // observations; only then does parity-1 uniquely mean phase 15.
        __syncwarp();
        MBARRIER_WAIT_PARITY(CSM + 8 * 0, 1);
        MBARRIER_WAIT_PARITY(CSM + 8 * 1, 1);
        for (int idx = lane; idx < 4096; idx += 32)
            cp_async16(WOS + (uint32_t)idx * 16, g_Wo + idx * 8);
        cp_commit();
        cp_wait<0>();
    } else {
        // ---------------- consumer warps (0..7) ----------------
        MBARRIER_WAIT_PARITY(MBQ, 0);

        // Q A-fragments: rows [warp*16, warp*16+16), 8 k-chunks of 16
        {
            int Rq = warp * 16 + (mi & 1) * 8 + r8;
            uint32_t qb = QS + (uint32_t)Rq * 256;
            int s7 = Rq & 7;
#pragma unroll
            for (int kc = 0; kc < 8; kc++)
                ldsm_x4(qa[kc], qb + (uint32_t)(((kc * 2 + (mi >> 1)) ^ s7) << 4));
        }

        float O[16][4];
#pragma unroll
        for (int n = 0; n < 16; n++)
#pragma unroll
            for (int j = 0; j < 4; j++) O[n][j] = 0.0f;
        float rs0 = 0.0f, rs1 = 0.0f;

        const int Rk_ = (mi >> 1) * 8 + r8;   // K fragment row (+ p*16)
        const int Rg_ = (mi & 1) * 8 + r8;    // G fragment row (+ p*16)
        const int ck_ = (mi & 1);             // K chunk offset
        const int cg_ = (mi >> 1);            // G chunk offset

        for (int kt = 0; kt < 64; kt++) {
            const int s = kt & 3;
            MBARRIER_WAIT_PARITY(RDY + 8 * s, (kt >> 2) & 1);
            const uint32_t kb = kstage(s);
            const uint32_t gb = gstage(s);

            // S = Q @ K^T  (16 x 64 per warp, in registers)
            float S[8][4];
#pragma unroll
            for (int n = 0; n < 8; n++)
#pragma unroll
                for (int j = 0; j < 4; j++) S[n][j] = 0.0f;

#pragma unroll
            for (int p = 0; p < 4; p++) {
                const int Rk = p * 16 + Rk_;
                const uint32_t kbp = kb + (uint32_t)Rk * 256;
                const int s7 = Rk & 7;
#pragma unroll
                for (int kc = 0; kc < 8; kc++) {
                    uint32_t f[4];
                    ldsm_x4(f, kbp + (uint32_t)(((kc * 2 + ck_) ^ s7) << 4));
                    mma16816(S[2 * p],     qa[kc], f[0], f[1]);
                    mma16816(S[2 * p + 1], qa[kc], f[2], f[3]);
                }
            }

            // P = exp2(S); pack to bf16x2 A-fragments; accumulate row sums
            uint32_t pa[4][4];
#pragma unroll
            for (int p = 0; p < 4; p++) {
                float e00 = ex2f(S[2 * p][0]),     e01 = ex2f(S[2 * p][1]);
                float e02 = ex2f(S[2 * p][2]),     e03 = ex2f(S[2 * p][3]);
                float e10 = ex2f(S[2 * p + 1][0]), e11 = ex2f(S[2 * p + 1][1]);
                float e12 = ex2f(S[2 * p + 1][2]), e13 = ex2f(S[2 * p + 1][3]);
                rs0 += (e00 + e01) + (e10 + e11);
                rs1 += (e02 + e03) + (e12 + e13);
                pa[p][0] = pack2(e00, e01);
                pa[p][1] = pack2(e02, e03);
                pa[p][2] = pack2(e10, e11);
                pa[p][3] = pack2(e12, e13);
            }

            // O += P @ G  (16 x 128 per warp)
#pragma unroll
            for (int p = 0; p < 4; p++) {
                const int Rg = p * 16 + Rg_;
                const uint32_t gbp = gb + (uint32_t)Rg * 256;
                const int s7 = Rg & 7;
#pragma unroll
                for (int j2 = 0; j2 < 8; j2++) {
                    uint32_t f[4];
                    ldsm_x4_t(f, gbp + (uint32_t)(((j2 * 2 + cg_) ^ s7) << 4));
                    mma16816(O[2 * j2],     pa[p], f[0], f[1]);
                    mma16816(O[2 * j2 + 1], pa[p], f[2], f[3]);
                }
            }

            MBARRIER_ARRIVE(CSM + 8 * s);      // all 32 lanes arrive
        }

        // finalize: row sums, normalize, write Y (bf16, swizzled) to Q region
        rs0 += __shfl_xor_sync(0xffffffff, rs0, 1);
        rs0 += __shfl_xor_sync(0xffffffff, rs0, 2);
        rs1 += __shfl_xor_sync(0xffffffff, rs1, 1);
        rs1 += __shfl_xor_sync(0xffffffff, rs1, 2);
        const float inv0 = 1.0f / rs0;
        const float inv1 = 1.0f / rs1;

        {
            int R0 = warp * 16 + rA;
            int R1 = R0 + 8;
            char* y0 = sm + 1024 + R0 * 256;
            char* y1 = sm + 1024 + R1 * 256;
            int x0 = R0 & 7, x1 = R1 & 7;
#pragma unroll
            for (int n = 0; n < 16; n++) {
                *(uint32_t*)(y0 + ((n ^ x0) << 4) + cA * 2) =
                    pack2(O[n][0] * inv0, O[n][1] * inv0);
                *(uint32_t*)(y1 + ((n ^ x1) << 4) + cA * 2) =
                    pack2(O[n][2] * inv1, O[n][3] * inv1);
            }
        }
        __syncwarp();

        // reload qa as Y fragments (same rows, same addressing as Q)
        {
            int Rq = warp * 16 + (mi & 1) * 8 + r8;
            uint32_t qb = QS + (uint32_t)Rq * 256;
            int s7 = Rq & 7;
#pragma unroll
            for (int kc = 0; kc < 8; kc++)
                ldsm_x4(qa[kc], qb + (uint32_t)(((kc * 2 + (mi >> 1)) ^ s7) << 4));
        }
    }

    // single barrier: Wo resident (producer waited cp groups) + Y fragments held
    __syncthreads();
    if (warp == 8) return;                 // producer done

    // ---------------- fused output projection ----------------
    // out[b,o,q0+s] = x[b,o,q0+s] + b_out[o] + sum_c Y[s][c]*Wo[c][o]
    const float* xb = x + (size_t)b * C * NHW + q0;
    float*       ob = out + (size_t)b * C * NHW + q0;
    const int Rg_ = (mi & 1) * 8 + r8;     // Wo fragment row (+ p*16)
    const int cg_ = (mi >> 1);             // Wo chunk offset
    const int sA0 = warp * 16 + rA;        // s for c[0],c[1]
    const int sA1 = sA0 + 8;               // s for c[2],c[3]

#pragma unroll
    for (int j2 = 0; j2 < 16; j2++) {      // 16 o-tiles of 16
        float c0[4] = {0.f, 0.f, 0.f, 0.f};
        float c1[4] = {0.f, 0.f, 0.f, 0.f};
#pragma unroll
        for (int p = 0; p < 8; p++) {      // k = c, 8 chunks of 16
            const int Rc = p * 16 + Rg_;
            uint32_t a = WOS + (uint32_t)Rc * 512 +
                         (uint32_t)(((j2 * 2 + cg_) ^ (Rc & 7)) << 4);
            uint32_t f[4];
            ldsm_x4_t(f, a);
            mma16816(c0, qa[p], f[0], f[1]);
            mma16816(c1, qa[p], f[2], f[3]);
        }
        const int o0 = j2 * 16 + cA;       // cols o0, o0+1
        const int o1 = o0 + 8;             // cols o1, o1+1
        float b0 = b_out[o0], b0p = b_out[o0 + 1];
        float b1 = b_out[o1], b1p = b_out[o1 + 1];
        ob[(size_t)o0 * NHW + sA0]       = c0[0] + b0  + xb[(size_t)o0 * NHW + sA0];
        ob[(size_t)(o0 + 1) * NHW + sA0] = c0[1] + b0p + xb[(size_t)(o0 + 1) * NHW + sA0];
        ob[(size_t)o0 * NHW + sA1]       = c0[2] + b0  + xb[(size_t)o0 * NHW + sA1];
        ob[(size_t)(o0 + 1) * NHW + sA1] = c0[3] + b0p + xb[(size_t)(o0 + 1) * NHW + sA1];
        ob[(size_t)o1 * NHW + sA0]       = c1[0] + b1  + xb[(size_t)o1 * NHW + sA0];
        ob[(size_t)(o1 + 1) * NHW + sA0] = c1[1] + b1p + xb[(size_t)(o1 + 1) * NHW + sA0];
        ob[(size_t)o1 * NHW + sA1]       = c1[2] + b1  + xb[(size_t)o1 * NHW + sA1];
        ob[(size_t)(o1 + 1) * NHW + sA1] = c1[3] + b1p + xb[(size_t)(o1 + 1) * NHW + sA1];
    }
}

// ---------------------------------------------------------------------------
extern "C" void kernel_launch(void* const* d_in, const int* in_sizes, int n_in,
                              void* d_out, int out_size)
{
    const float* x       = (const float*)d_in[0];
    const float* w_g     = (const float*)d_in[1];
    const float* b_g     = (const float*)d_in[2];
    const float* w_theta = (const float*)d_in[3];
    const float* b_theta = (const float*)d_in[4];
    const float* w_phi   = (const float*)d_in[5];
    const float* b_phi   = (const float*)d_in[6];
    const float* w_out   = (const float*)d_in[7];
    const float* b_out   = (const float*)d_in[8];
    float* out = (float*)d_out;

    cudaFuncSetAttribute(proj_kernel, cudaFuncAttributeMaxDynamicSharedMemorySize, 95232);
    cudaFuncSetAttribute(attn_kernel, cudaFuncAttributeMaxDynamicSharedMemorySize, 164864);

    cvt_w_kernel<<<129, 256>>>(w_theta, b_theta, w_phi, b_phi, w_g, b_g, w_out);

    dim3 pgrid(64, 2, NB);
    proj_kernel<<<pgrid, 256, 95232>>>(x);

    dim3 agrid(32, NB);
    attn_kernel<<<agrid, 288, 164864>>>(x, b_out, out);
}

// round 17
// speedup vs baseline: 1.0159x; 1.0156x over previous
#include <cuda_runtime.h>
#include <cuda_bf16.h>
#include <mma.h>
#include <stdint.h>

using namespace nvcuda;

#define NB  4
#define C   256
#define CI  128
#define NHW 4096
// theta scale: sqrt(128) (reference divides by d**-0.5) * log2(e) (attn uses ex2)
#define SCALE2 16.32374202690664f

// Scratch (allocation-free). Q/K/G (and Wo) stored PRE-SWIZZLED: within each
// row, 16B chunk c is stored at position c ^ (row & 7). Tiles become
// contiguous blocks for cp.async.bulk and conflict-free for ldmatrix.
__device__ __nv_bfloat16 g_Xb[NB * C * NHW];   // bf16 copy of x
__device__ __nv_bfloat16 g_W[C * 384];         // fused weights, [c][o] (theta|phi|g)
__device__ float         g_bias[384];
__device__ __nv_bfloat16 g_Wo[CI * 256];       // w_out transposed bf16, [cc][o] (swizzled)
__device__ __nv_bfloat16 g_Q[NB * NHW * CI];   // theta, pre-scaled by SCALE2 (swizzled)
__device__ __nv_bfloat16 g_K[NB * NHW * CI];   // phi (swizzled)
__device__ __nv_bfloat16 g_G[NB * NHW * CI];   // g (swizzled)

// ---------------------------------------------------------------------------
// helpers
// ---------------------------------------------------------------------------
__device__ __forceinline__ uint32_t pack2(float a, float b) {
    __nv_bfloat162 h = __floats2bfloat162_rn(a, b);
    return *reinterpret_cast<uint32_t*>(&h);
}
__device__ __forceinline__ float ex2f(float x) {
    float y;
    asm("ex2.approx.f32 %0, %1;" : "=f"(y) : "f"(x));
    return y;
}
__device__ __forceinline__ void ldsm_x4(uint32_t* f, uint32_t addr) {
    asm volatile("ldmatrix.sync.aligned.m8n8.x4.shared.b16 {%0,%1,%2,%3}, [%4];"
                 : "=r"(f[0]), "=r"(f[1]), "=r"(f[2]), "=r"(f[3]) : "r"(addr));
}
__device__ __forceinline__ void ldsm_x4_t(uint32_t* f, uint32_t addr) {
    asm volatile("ldmatrix.sync.aligned.m8n8.x4.trans.shared.b16 {%0,%1,%2,%3}, [%4];"
                 : "=r"(f[0]), "=r"(f[1]), "=r"(f[2]), "=r"(f[3]) : "r"(addr));
}
__device__ __forceinline__ void mma16816(float* c, const uint32_t* a,
                                         uint32_t b0, uint32_t b1) {
    asm volatile("mma.sync.aligned.m16n8k16.row.col.f32.bf16.bf16.f32 "
                 "{%0,%1,%2,%3}, {%4,%5,%6,%7}, {%8,%9}, {%0,%1,%2,%3};"
                 : "+f"(c[0]), "+f"(c[1]), "+f"(c[2]), "+f"(c[3])
                 : "r"(a[0]), "r"(a[1]), "r"(a[2]), "r"(a[3]), "r"(b0), "r"(b1));
}
__device__ __forceinline__ void cp_async16(uint32_t dst, const void* src) {
    asm volatile("cp.async.cg.shared.global [%0], [%1], 16;" :: "r"(dst), "l"(src));
}
__device__ __forceinline__ void cp_commit() { asm volatile("cp.async.commit_group;"); }
template <int N>
__device__ __forceinline__ void cp_wait() {
    asm volatile("cp.async.wait_group %0;" :: "n"(N) : "memory");
}
// 1D bulk copy, global -> shared, mbarrier completion (sm_90 baseline PTX)
__device__ __forceinline__ void cp_bulk(uint32_t dst, const void* src,
                                        uint32_t bytes, uint32_t mbar) {
    asm volatile(
        "cp.async.bulk.shared::cluster.global.mbarrier::complete_tx::bytes "
        "[%0], [%1], %2, [%3];"
        :: "r"(dst), "l"(src), "r"(bytes), "r"(mbar) : "memory");
}

#define MBARRIER_INIT(mbar, cnt) \
    asm volatile("mbarrier.init.shared.b64 [%0], %1;" \
                 :: "r"((uint32_t)(mbar)), "r"((uint32_t)(cnt)) : "memory")
#define MBARRIER_EXPECT_TX(mbar, tx) \
    asm volatile("mbarrier.arrive.expect_tx.shared.b64 _, [%0], %1;" \
                 :: "r"((uint32_t)(mbar)), "r"((uint32_t)(tx)) : "memory")
#define MBARRIER_ARRIVE(mbar) \
    asm volatile("mbarrier.arrive.shared.b64 _, [%0];" \
                 :: "r"((uint32_t)(mbar)) : "memory")
#define MBARRIER_WAIT_PARITY(mbar, parity) do { \
    uint32_t _m = (uint32_t)(mbar); uint32_t _p = (uint32_t)(parity); uint32_t _d; \
    asm volatile("{\n\t.reg .pred p;\n\t" \
        "mbarrier.try_wait.parity.acquire.cta.shared::cta.b64 p, [%1], %2;\n\t" \
        "selp.b32 %0, 1, 0, p;\n\t}" : "=r"(_d) : "r"(_m), "r"(_p) : "memory"); \
    if (!_d) { \
        asm volatile("{\n\t.reg .pred P1;\n\t" \
            "WAIT_LOOP_%=:\n\t" \
            "mbarrier.try_wait.parity.acquire.cta.shared::cta.b64 P1, [%0], %1, 0x989680;\n\t" \
            "@P1 bra.uni WAIT_DONE_%=;\n\t" \
            "bra.uni WAIT_LOOP_%=;\n\t" \
            "WAIT_DONE_%=:\n\t}" :: "r"(_m), "r"(_p) : "memory"); \
    } \
} while (0)

// ---------------------------------------------------------------------------
// Kernel 0: ALL input conversions in one launch.
//   blocks [0,1024):     x -> bf16 (8 floats / thread / iter, 16B stores)
//   blocks [1024,1120):  g_W via coalesced 32x32 smem transposes (96 tiles)
//   blocks [1120,1152):  g_Wo via coalesced transposes, chunk-swizzled (32)
//   block  1152:         bias vector
// ---------------------------------------------------------------------------
__global__ void __launch_bounds__(256) cvt_all_kernel(
        const float* __restrict__ x,
        const float* __restrict__ w_theta, const float* __restrict__ b_theta,
        const float* __restrict__ w_phi,   const float* __restrict__ b_phi,
        const float* __restrict__ w_g,     const float* __restrict__ b_g,
        const float* __restrict__ w_out)
{
    __shared__ float tile[32][33];
    const int blk = blockIdx.x;
    const int t = threadIdx.x;

    if (blk < 1024) {
        const int n8 = NB * C * NHW / 8;
        for (int i = blk * 256 + t; i < n8; i += 1024 * 256) {
            float4 a = *(const float4*)(x + (size_t)i * 8);
            float4 b = *(const float4*)(x + (size_t)i * 8 + 4);
            uint4 w = make_uint4(pack2(a.x, a.y), pack2(a.z, a.w),
                                 pack2(b.x, b.y), pack2(b.z, b.w));
            *(uint4*)(g_Xb + (size_t)i * 8) = w;
        }
    } else if (blk < 1120) {
        // g_W[c*384+o] = fused[o][c] (theta*SCALE2 | phi | g)
        const int b1 = blk - 1024;
        const int ct = b1 & 7;           // c-tile 0..7
        const int ot = b1 >> 3;          // o-tile 0..11
        const int c0 = ct * 32, o0 = ot * 32;
#pragma unroll
        for (int i = 0; i < 4; i++) {    // load coalesced over c
            int idx = t + i * 256;
            int oo = idx >> 5, cc = idx & 31;
            int o = o0 + oo;
            float v;
            if (o < 128)      v = w_theta[o * C + c0 + cc] * SCALE2;
            else if (o < 256) v = w_phi[(o - 128) * C + c0 + cc];
            else              v = w_g[(o - 256) * C + c0 + cc];
            tile[oo][cc] = v;
        }
        __syncthreads();
#pragma unroll
        for (int i = 0; i < 4; i++) {    // write coalesced over o
            int idx = t + i * 256;
            int cc = idx >> 5, oo = idx & 31;
            g_W[(c0 + cc) * 384 + o0 + oo] = __float2bfloat16(tile[oo][cc]);
        }
    } else if (blk < 1152) {
        // g_Wo[cc*256+phys(o,cc)] = w_out[o][cc], chunk-swizzled rows
        const int b2 = blk - 1120;
        const int ccT = b2 & 3;          // cc-tile 0..3
        const int oT  = b2 >> 2;         // o-tile 0..7
        const int cc0 = ccT * 32, o0 = oT * 32;
#pragma unroll
        for (int i = 0; i < 4; i++) {
            int idx = t + i * 256;
            int oo = idx >> 5, cc = idx & 31;
            tile[oo][cc] = w_out[(o0 + oo) * CI + cc0 + cc];
        }
        __syncthreads();
#pragma unroll
        for (int i = 0; i < 4; i++) {
            int idx = t + i * 256;
            int cc = idx >> 5, oo = idx & 31;
            int o = o0 + oo;
            int ccg = cc0 + cc;
            int phys = (((o >> 3) ^ (ccg & 7)) << 3) + (o & 7);
            g_Wo[ccg * 256 + phys] = __float2bfloat16(tile[oo][cc]);
        }
    } else {
        for (int o = t; o < 384; o += 256) {
            float bv;
            if (o < 128)      bv = b_theta[o] * SCALE2;
            else if (o < 256) bv = b_phi[o - 128];
            else              bv = b_g[o - 256];
            g_bias[o] = bv;
        }
    }
}

// ---------------------------------------------------------------------------
// Kernel 1: projections GEMM (round-13 proven version: reads bf16 g_Xb).
// T[s,o] = sum_c Xb[c,s]*W[c,o] (+bias, route to Q/K/G pre-swizzled).
// grid (64 stile, 2 nsplit, 4 b), 256 threads. dyn smem = 69632 B.
// ---------------------------------------------------------------------------
__global__ void __launch_bounds__(256) proj_kernel()
{
    extern __shared__ char sm[];
    uint32_t sb = (uint32_t)__cvta_generic_to_shared(sm);
    const uint32_t xs0 = sb;
    const uint32_t xs1 = sb + 9216;
    const uint32_t ws0 = sb + 18432;
    const uint32_t ws1 = sb + 44032;
    float* St = (float*)sm;                         // [64][200] fp32 (reuse)

    const int s0 = blockIdx.x * 64;
    const int ng = blockIdx.y;
    const int b  = blockIdx.z;
    const int t  = threadIdx.x;
    const int warp = t >> 5;
    const int wm = warp >> 1;
    const int wn = warp & 1;

    const __nv_bfloat16* Xg = g_Xb + (size_t)b * C * NHW;

    auto prefetch = [&](int c0, uint32_t xd, uint32_t wd) {
#pragma unroll
        for (int i = 0; i < 2; i++) {           // X: 512 chunks of 16B
            int idx = t + i * 256;
            int rr = idx >> 3, c8 = (idx & 7) * 8;
            cp_async16(xd + (rr * 72 + c8) * 2, Xg + (size_t)(c0 + rr) * NHW + s0 + c8);
        }
#pragma unroll
        for (int i = 0; i < 6; i++) {           // W: 1536 chunks
            int idx = t + i * 256;
            int rr = idx / 24, o8 = (idx % 24) * 8;
            cp_async16(wd + (rr * 200 + o8) * 2, g_W + (c0 + rr) * 384 + ng * 192 + o8);
        }
    };
    prefetch(0, xs0, ws0);  cp_commit();
    prefetch(64, xs1, ws1); cp_commit();

    wmma::fragment<wmma::accumulator, 16, 16, 16, float> acc[6];
#pragma unroll
    for (int j = 0; j < 6; j++) wmma::fill_fragment(acc[j], 0.0f);

    for (int kc = 0; kc < 4; kc++) {
        cp_wait<1>();
        __syncthreads();
        const __nv_bfloat16* Xs = (const __nv_bfloat16*)(sm + ((kc & 1) ? 9216 : 0));
        const __nv_bfloat16* Ws = (const __nv_bfloat16*)(sm + 18432 + ((kc & 1) ? 25600 : 0));
#pragma unroll
        for (int kk = 0; kk < 4; kk++) {
            wmma::fragment<wmma::matrix_a, 16, 16, 16, __nv_bfloat16, wmma::col_major> af;
            wmma::load_matrix_sync(af, Xs + (kk * 16) * 72 + wm * 16, 72);
#pragma unroll
            for (int j = 0; j < 6; j++) {
                wmma::fragment<wmma::matrix_b, 16, 16, 16, __nv_bfloat16, wmma::row_major> bf;
                wmma::load_matrix_sync(bf, Ws + (kk * 16) * 200 + wn * 96 + j * 16, 200);
                wmma::mma_sync(acc[j], af, bf, acc[j]);
            }
        }
        __syncthreads();
        if (kc + 2 < 4)
            prefetch((kc + 2) * 64, (kc & 1) ? xs1 : xs0, (kc & 1) ? ws1 : ws0);
        cp_commit();
    }

#pragma unroll
    for (int j = 0; j < 6; j++)
        wmma::store_matrix_sync(St + (wm * 16) * 200 + wn * 96 + j * 16, acc[j], 200,
                                wmma::mem_row_major);
    __syncthreads();

    // bias + route to Q/K/G, paired stores. Swizzle: chunk (col>>3)^(row&7).
    for (int i = 0; i < 24; i++) {
        int idx = t + i * 256;               // 6144 = 64s * 96 col-pairs
        int ss = idx / 96;
        int op = idx % 96;
        int oc = op * 2;
        int ocg = ng * 192 + oc;
        float v0 = St[ss * 200 + oc]     + g_bias[ocg];
        float v1 = St[ss * 200 + oc + 1] + g_bias[ocg + 1];
        uint32_t w = pack2(v0, v1);
        size_t base = ((size_t)b * NHW + s0 + ss) * CI;
        int r7 = ss & 7;
        int col = (ocg < 128) ? ocg : (ocg < 256 ? ocg - 128 : ocg - 256);
        int phys = (((col >> 3) ^ r7) << 3) + (col & 7);
        if (ocg < 128)       *(uint32_t*)&g_Q[base + phys] = w;
        else if (ocg < 256)  *(uint32_t*)&g_K[base + phys] = w;
        else                 *(uint32_t*)&g_G[base + phys] = w;
    }
}

// ---------------------------------------------------------------------------
// Kernel 2: warp-specialized flash attention WITH FUSED OUTPUT PROJECTION.
// Identical to the round-13/16 PASSING version (producer __syncwarp fix).
// grid (32, 4) = 128 CTAs, 288 threads, dyn smem = 164864 B.
// ---------------------------------------------------------------------------
__global__ void __launch_bounds__(288) attn_kernel(
        const float* __restrict__ x,
        const float* __restrict__ b_out, float* __restrict__ out)
{
    extern __shared__ char sm[];
    uint32_t sb = (uint32_t)__cvta_generic_to_shared(sm);
    const uint32_t MBQ = sb;             // Q ready barrier
    const uint32_t RDY = sb + 16;        // ready[4] at +16,+24,+32,+40
    const uint32_t CSM = sb + 64;        // consumed[4] at +64,+72,+80,+88
    const uint32_t QS  = sb + 1024;      // Q / later Y: 128 rows x 256B = 32768
    auto kstage = [&](int s) { return QS + 32768u + (uint32_t)s * 32768u; };
    auto gstage = [&](int s) { return QS + 32768u + (uint32_t)s * 32768u + 16384u; };
    const uint32_t WOS = QS + 32768u;    // Wo (epilogue): 128 x 512B = 65536 (stages 0-1)

    const int b  = blockIdx.y;
    const int q0 = blockIdx.x * 128;
    const int t  = threadIdx.x;
    const int warp = t >> 5;
    const int lane = t & 31;
    const int mi = lane >> 3;
    const int r8 = lane & 7;
    const int rA = lane >> 2;
    const int cA = (lane & 3) * 2;

    const __nv_bfloat16* Qg = g_Q + ((size_t)b * NHW + q0) * CI;
    const __nv_bfloat16* Kb = g_K + (size_t)b * NHW * CI;
    const __nv_bfloat16* Gb = g_G + (size_t)b * NHW * CI;

    if (t == 0) {
        MBARRIER_INIT(MBQ, 1);
#pragma unroll
        for (int s = 0; s < 4; s++) {
            MBARRIER_INIT(RDY + 8 * s, 1);
            MBARRIER_INIT(CSM + 8 * s, 256);   // 8 consumer warps x 32 lanes
        }
    }
    __syncthreads();

    uint32_t qa[8][4];                    // Q fragments; reused for Y fragments

    if (warp == 8) {
        // ---------------- producer warp ----------------
        if (lane == 0) {
            MBARRIER_EXPECT_TX(MBQ, 32768);
            cp_bulk(QS, Qg, 32768, MBQ);
            for (int kt = 0; kt < 64; kt++) {
                int s = kt & 3;
                if (kt >= 4)
                    MBARRIER_WAIT_PARITY(CSM + 8 * s, ((kt >> 2) + 1) & 1);
                MBARRIER_EXPECT_TX(RDY + 8 * s, 32768);
                cp_bulk(kstage(s), Kb + (size_t)kt * 64 * CI, 16384, RDY + 8 * s);
                cp_bulk(gstage(s), Gb + (size_t)kt * 64 * CI, 16384, RDY + 8 * s);
            }
        }
        // Order ALL producer lanes behind lane 0's sequential phase
        // observations; only then does parity-1 uniquely mean phase 15.
        __syncwarp();
        MBARRIER_WAIT_PARITY(CSM + 8 * 0, 1);
        MBARRIER_WAIT_PARITY(CSM + 8 * 1, 1);
        for (int idx = lane; idx < 4096; idx += 32)
            cp_async16(WOS + (uint32_t)idx * 16, g_Wo + idx * 8);
        cp_commit();
        cp_wait<0>();
    } else {
        // ---------------- consumer warps (0..7) ----------------
        MBARRIER_WAIT_PARITY(MBQ, 0);

        // Q A-fragments: rows [warp*16, warp*16+16), 8 k-chunks of 16
        {
            int Rq = warp * 16 + (mi & 1) * 8 + r8;
            uint32_t qb = QS + (uint32_t)Rq * 256;
            int s7 = Rq & 7;
#pragma unroll
            for (int kc = 0; kc < 8; kc++)
                ldsm_x4(qa[kc], qb + (uint32_t)(((kc * 2 + (mi >> 1)) ^ s7) << 4));
        }

        float O[16][4];
#pragma unroll
        for (int n = 0; n < 16; n++)
#pragma unroll
            for (int j = 0; j < 4; j++) O[n][j] = 0.0f;
        float rs0 = 0.0f, rs1 = 0.0f;

        const int Rk_ = (mi >> 1) * 8 + r8;   // K fragment row (+ p*16)
        const int Rg_ = (mi & 1) * 8 + r8;    // G fragment row (+ p*16)
        const int ck_ = (mi & 1);             // K chunk offset
        const int cg_ = (mi >> 1);            // G chunk offset

        for (int kt = 0; kt < 64; kt++) {
            const int s = kt & 3;
            MBARRIER_WAIT_PARITY(RDY + 8 * s, (kt >> 2) & 1);
            const uint32_t kb = kstage(s);
            const uint32_t gb = gstage(s);

            // S = Q @ K^T  (16 x 64 per warp, in registers)
            float S[8][4];
#pragma unroll
            for (int n = 0; n < 8; n++)
#pragma unroll
                for (int j = 0; j < 4; j++) S[n][j] = 0.0f;

#pragma unroll
            for (int p = 0; p < 4; p++) {
                const int Rk = p * 16 + Rk_;
                const uint32_t kbp = kb + (uint32_t)Rk * 256;
                const int s7 = Rk & 7;
#pragma unroll
                for (int kc = 0; kc < 8; kc++) {
                    uint32_t f[4];
                    ldsm_x4(f, kbp + (uint32_t)(((kc * 2 + ck_) ^ s7) << 4));
                    mma16816(S[2 * p],     qa[kc], f[0], f[1]);
                    mma16816(S[2 * p + 1], qa[kc], f[2], f[3]);
                }
            }

            // P = exp2(S); pack to bf16x2 A-fragments; accumulate row sums
            uint32_t pa[4][4];
#pragma unroll
            for (int p = 0; p < 4; p++) {
                float e00 = ex2f(S[2 * p][0]),     e01 = ex2f(S[2 * p][1]);
                float e02 = ex2f(S[2 * p][2]),     e03 = ex2f(S[2 * p][3]);
                float e10 = ex2f(S[2 * p + 1][0]), e11 = ex2f(S[2 * p + 1][1]);
                float e12 = ex2f(S[2 * p + 1][2]), e13 = ex2f(S[2 * p + 1][3]);
                rs0 += (e00 + e01) + (e10 + e11);
                rs1 += (e02 + e03) + (e12 + e13);
                pa[p][0] = pack2(e00, e01);
                pa[p][1] = pack2(e02, e03);
                pa[p][2] = pack2(e10, e11);
                pa[p][3] = pack2(e12, e13);
            }

            // O += P @ G  (16 x 128 per warp)
#pragma unroll
            for (int p = 0; p < 4; p++) {
                const int Rg = p * 16 + Rg_;
                const uint32_t gbp = gb + (uint32_t)Rg * 256;
                const int s7 = Rg & 7;
#pragma unroll
                for (int j2 = 0; j2 < 8; j2++) {
                    uint32_t f[4];
                    ldsm_x4_t(f, gbp + (uint32_t)(((j2 * 2 + cg_) ^ s7) << 4));
                    mma16816(O[2 * j2],     pa[p], f[0], f[1]);
                    mma16816(O[2 * j2 + 1], pa[p], f[2], f[3]);
                }
            }

            MBARRIER_ARRIVE(CSM + 8 * s);      // all 32 lanes arrive
        }

        // finalize: row sums, normalize, write Y (bf16, swizzled) to Q region
        rs0 += __shfl_xor_sync(0xffffffff, rs0, 1);
        rs0 += __shfl_xor_sync(0xffffffff, rs0, 2);
        rs1 += __shfl_xor_sync(0xffffffff, rs1, 1);
        rs1 += __shfl_xor_sync(0xffffffff, rs1, 2);
        const float inv0 = 1.0f / rs0;
        const float inv1 = 1.0f / rs1;

        {
            int R0 = warp * 16 + rA;
            int R1 = R0 + 8;
            char* y0 = sm + 1024 + R0 * 256;
            char* y1 = sm + 1024 + R1 * 256;
            int x0 = R0 & 7, x1 = R1 & 7;
#pragma unroll
            for (int n = 0; n < 16; n++) {
                *(uint32_t*)(y0 + ((n ^ x0) << 4) + cA * 2) =
                    pack2(O[n][0] * inv0, O[n][1] * inv0);
                *(uint32_t*)(y1 + ((n ^ x1) << 4) + cA * 2) =
                    pack2(O[n][2] * inv1, O[n][3] * inv1);
            }
        }
        __syncwarp();

        // reload qa as Y fragments (same rows, same addressing as Q)
        {
            int Rq = warp * 16 + (mi & 1) * 8 + r8;
            uint32_t qb = QS + (uint32_t)Rq * 256;
            int s7 = Rq & 7;
#pragma unroll
            for (int kc = 0; kc < 8; kc++)
                ldsm_x4(qa[kc], qb + (uint32_t)(((kc * 2 + (mi >> 1)) ^ s7) << 4));
        }
    }

    // single barrier: Wo resident (producer waited cp groups) + Y fragments held
    __syncthreads();
    if (warp == 8) return;                 // producer done

    // ---------------- fused output projection ----------------
    // out[b,o,q0+s] = x[b,o,q0+s] + b_out[o] + sum_c Y[s][c]*Wo[c][o]
    const float* xb = x + (size_t)b * C * NHW + q0;
    float*       ob = out + (size_t)b * C * NHW + q0;
    const int Rg_ = (mi & 1) * 8 + r8;     // Wo fragment row (+ p*16)
    const int cg_ = (mi >> 1);             // Wo chunk offset
    const int sA0 = warp * 16 + rA;        // s for c[0],c[1]
    const int sA1 = sA0 + 8;               // s for c[2],c[3]

#pragma unroll
    for (int j2 = 0; j2 < 16; j2++) {      // 16 o-tiles of 16
        float c0[4] = {0.f, 0.f, 0.f, 0.f};
        float c1[4] = {0.f, 0.f, 0.f, 0.f};
#pragma unroll
        for (int p = 0; p < 8; p++) {      // k = c, 8 chunks of 16
            const int Rc = p * 16 + Rg_;
            uint32_t a = WOS + (uint32_t)Rc * 512 +
                         (uint32_t)(((j2 * 2 + cg_) ^ (Rc & 7)) << 4);
            uint32_t f[4];
            ldsm_x4_t(f, a);
            mma16816(c0, qa[p], f[0], f[1]);
            mma16816(c1, qa[p], f[2], f[3]);
        }
        const int o0 = j2 * 16 + cA;       // cols o0, o0+1
        const int o1 = o0 + 8;             // cols o1, o1+1
        float b0 = b_out[o0], b0p = b_out[o0 + 1];
        float b1 = b_out[o1], b1p = b_out[o1 + 1];
        ob[(size_t)o0 * NHW + sA0]       = c0[0] + b0  + xb[(size_t)o0 * NHW + sA0];
        ob[(size_t)(o0 + 1) * NHW + sA0] = c0[1] + b0p + xb[(size_t)(o0 + 1) * NHW + sA0];
        ob[(size_t)o0 * NHW + sA1]       = c0[2] + b0  + xb[(size_t)o0 * NHW + sA1];
        ob[(size_t)(o0 + 1) * NHW + sA1] = c0[3] + b0p + xb[(size_t)(o0 + 1) * NHW + sA1];
        ob[(size_t)o1 * NHW + sA0]       = c1[0] + b1  + xb[(size_t)o1 * NHW + sA0];
        ob[(size_t)(o1 + 1) * NHW + sA0] = c1[1] + b1p + xb[(size_t)(o1 + 1) * NHW + sA0];
        ob[(size_t)o1 * NHW + sA1]       = c1[2] + b1  + xb[(size_t)o1 * NHW + sA1];
        ob[(size_t)(o1 + 1) * NHW + sA1] = c1[3] + b1p + xb[(size_t)(o1 + 1) * NHW + sA1];
    }
}

// ---------------------------------------------------------------------------
extern "C" void kernel_launch(void* const* d_in, const int* in_sizes, int n_in,
                              void* d_out, int out_size)
{
    const float* x       = (const float*)d_in[0];
    const float* w_g     = (const float*)d_in[1];
    const float* b_g     = (const float*)d_in[2];
    const float* w_theta = (const float*)d_in[3];
    const float* b_theta = (const float*)d_in[4];
    const float* w_phi   = (const float*)d_in[5];
    const float* b_phi   = (const float*)d_in[6];
    const float* w_out   = (const float*)d_in[7];
    const float* b_out   = (const float*)d_in[8];
    float* out = (float*)d_out;

    cudaFuncSetAttribute(proj_kernel, cudaFuncAttributeMaxDynamicSharedMemorySize, 69632);
    cudaFuncSetAttribute(attn_kernel, cudaFuncAttributeMaxDynamicSharedMemorySize, 164864);

    cvt_all_kernel<<<1153, 256>>>(x, w_theta, b_theta, w_phi, b_phi, w_g, b_g, w_out);

    dim3 pgrid(64, 2, NB);
    proj_kernel<<<pgrid, 256, 69632>>>();

    dim3 agrid(32, NB);
    attn_kernel<<<agrid, 288, 164864>>>(x, b_out, out);
}